// round 9
// baseline (speedup 1.0000x reference)
#include <cuda_runtime.h>
#include <math.h>
#include <stdint.h>

#define BATCH 64
#define IC 32
#define OC 32
#define NM 64
#define HW 4096
#define CTRLD 512
#define ROWS 4160        // NF(64) + NI(2048) + NO(2048)
#define KSPLIT 4
#define BR (BATCH * ROWS)
#define OUT_ELEMS (BATCH * OC * HW)

__device__ float g_ctrl[KSPLIT * BR];   // partials [kz][row][batch]
__device__ float g_gates[BR];           // reduced [batch][row]

__device__ __forceinline__ float tanh_fast(float x) {
    float y;
    asm("tanh.approx.f32 %0, %1;" : "=f"(y) : "f"(x));
    return y;
}
__device__ __forceinline__ float round_tf32(float x) {
    uint32_t h;
    asm("cvt.rna.tf32.f32 %0, %1;" : "=r"(h) : "f"(x));
    return __uint_as_float(h);
}
__device__ __forceinline__ void mma_tf32(float* d, const float4 a, const float2 b) {
    asm("mma.sync.aligned.m16n8k8.row.col.f32.tf32.tf32.f32 "
        "{%0,%1,%2,%3},{%4,%5,%6,%7},{%8,%9},{%0,%1,%2,%3};"
        : "+f"(d[0]), "+f"(d[1]), "+f"(d[2]), "+f"(d[3])
        : "r"(__float_as_uint(a.x)), "r"(__float_as_uint(a.y)),
          "r"(__float_as_uint(a.z)), "r"(__float_as_uint(a.w)),
          "r"(__float_as_uint(b.x)), "r"(__float_as_uint(b.y)));
}

// ---------------------------------------------------------------------------
// Kernel 1: ctrl partials = controls @ W.T, grid (130, 4); 32 rows x 64 batch.
// Double-buffered chunks of 16; 4 CTAs/SM.
// ---------------------------------------------------------------------------
__global__ __launch_bounds__(256, 4) void ctrl_gemm(
    const float* __restrict__ controls,   // [64, 512]
    const float* __restrict__ W)          // [4160, 512]
{
    __shared__ float sW[2][16 * 36];   // [k][r], 32 rows pad 36
    __shared__ float sC[2][16 * 68];   // [k][b], 64 batch pad 68

    const int r0    = blockIdx.x * 32;
    const int kz    = blockIdx.y;
    const int kbase = kz * (CTRLD / KSPLIT);   // 128 per split
    const int tid   = threadIdx.x;
    const int ty    = tid >> 4;     // 0..15 -> 2 rows
    const int tx    = tid & 15;     // 0..15 -> 4 batches

    const int scr = tid >> 2;           // 0..63
    const int sck = (tid & 3) * 4;      // 0,4,8,12
    const float* cp = controls + scr * CTRLD + kbase + sck;
    const float* wp = W + (size_t)(r0 + (scr & 31)) * CTRLD + kbase + sck;
    const bool   wload = tid < 128;

    float acc[2][4] = {};

    // prologue
    {
        float4 cv = *(const float4*)cp;
        sC[0][(sck + 0) * 68 + scr] = cv.x;
        sC[0][(sck + 1) * 68 + scr] = cv.y;
        sC[0][(sck + 2) * 68 + scr] = cv.z;
        sC[0][(sck + 3) * 68 + scr] = cv.w;
        if (wload) {
            float4 wv = *(const float4*)wp;
            sW[0][(sck + 0) * 36 + scr] = wv.x;
            sW[0][(sck + 1) * 36 + scr] = wv.y;
            sW[0][(sck + 2) * 36 + scr] = wv.z;
            sW[0][(sck + 3) * 36 + scr] = wv.w;
        }
    }
    __syncthreads();

    #pragma unroll
    for (int c = 0; c < 8; c++) {
        const int cur = c & 1;
        const int nxt = cur ^ 1;

        float4 wv, cv;
        if (c < 7) {
            cv = *(const float4*)(cp + (c + 1) * 16);
            if (wload) wv = *(const float4*)(wp + (c + 1) * 16);
        }

        #pragma unroll
        for (int k = 0; k < 16; k++) {
            float2 a  = *(const float2*)&sW[cur][k * 36 + ty * 2];
            float4 bb = *(const float4*)&sC[cur][k * 68 + tx * 4];
            float bv[4] = {bb.x, bb.y, bb.z, bb.w};
            #pragma unroll
            for (int j = 0; j < 4; j++) {
                acc[0][j] = fmaf(a.x, bv[j], acc[0][j]);
                acc[1][j] = fmaf(a.y, bv[j], acc[1][j]);
            }
        }

        if (c < 7) {
            sC[nxt][(sck + 0) * 68 + scr] = cv.x;
            sC[nxt][(sck + 1) * 68 + scr] = cv.y;
            sC[nxt][(sck + 2) * 68 + scr] = cv.z;
            sC[nxt][(sck + 3) * 68 + scr] = cv.w;
            if (wload) {
                sW[nxt][(sck + 0) * 36 + scr] = wv.x;
                sW[nxt][(sck + 1) * 36 + scr] = wv.y;
                sW[nxt][(sck + 2) * 36 + scr] = wv.z;
                sW[nxt][(sck + 3) * 36 + scr] = wv.w;
            }
            __syncthreads();
        }
    }

    #pragma unroll
    for (int i = 0; i < 2; i++) {
        int r = r0 + ty * 2 + i;
        float4 v = make_float4(acc[i][0], acc[i][1], acc[i][2], acc[i][3]);
        *(float4*)&g_ctrl[(size_t)kz * BR + r * 64 + tx * 4] = v;
    }
}

// ---------------------------------------------------------------------------
// Kernel 1b: reduce 4 partials [kz][r][b], transpose -> g_gates [b][r].
// ---------------------------------------------------------------------------
__global__ __launch_bounds__(256) void ctrl_reduce_t()
{
    __shared__ float s[64 * 65];
    const int r0  = blockIdx.x * 64;
    const int tid = threadIdx.x;

    #pragma unroll
    for (int t = 0; t < 16; t++) {
        int i  = t * 256 + tid;
        int rr = i >> 6, b = i & 63;
        float v = 0.f;
        #pragma unroll
        for (int k = 0; k < KSPLIT; k++)
            v += g_ctrl[(size_t)k * BR + (r0 + rr) * 64 + b];
        s[rr * 65 + b] = v;
    }
    __syncthreads();

    #pragma unroll
    for (int t = 0; t < 16; t++) {
        int i  = t * 256 + tid;
        int b  = i >> 6, rr = i & 63;
        g_gates[(size_t)b * ROWS + r0 + rr] = s[rr * 65 + b];
    }
}

// ---------------------------------------------------------------------------
// Kernel 2: tensor-core vstm with fragment-packed SMEM.
//  s_inf : input tile in B-frag order [kk(4)][pb(16)][lane(32)][r(2)]
//  s_ginf: in-gates  in A-frag order [mt(4)][kk(4)][lane(32)][hi0..3,lo0..3]
//  s_gotf: out-gates in A-frag order [ot(2)][kk(8)][lane(32)][hi0..3]  (lo dropped)
//  s_t   : tanh tile [64][136] row layout (phase-2 B, scalar loads)
// ---------------------------------------------------------------------------
#define PIX_PAD 136

__global__ __launch_bounds__(512, 2) void vstm_main(
    const float* __restrict__ inputs,     // [B, 32, 4096]
    const float* __restrict__ state,      // [B, 64, 4096]
    float* __restrict__ outputs,          // [B, 32, 4096]
    float* __restrict__ new_state)        // [B, 64, 4096]
{
    extern __shared__ float sm[];
    float* s_inf  = sm;                    // 4096
    float* s_t    = s_inf + 4096;          // 8704
    float* s_ginf = s_t + 64 * PIX_PAD;    // 4096
    float* s_gotf = s_ginf + 4096;         // 2048
    float* s_f    = s_gotf + 2048;         // 64

    const int b    = blockIdx.y;
    const int p0   = blockIdx.x * 128;
    const int tid  = threadIdx.x;
    const int lane = tid & 31;
    const int w    = tid >> 5;       // 0..15
    const int g    = lane >> 2;      // 0..7
    const int tg   = lane & 3;       // 0..3

    // ---- stage gates into fragment order, splitting hi/lo once ----
    {
        const float* gc = g_gates + (size_t)b * ROWS;
        for (int i = tid; i < ROWS; i += 512) {
            float v  = gc[i];
            float hi = round_tf32(v);
            if (i < 64) {
                s_f[i] = v;
            } else if (i < 64 + 2048) {
                float lo = round_tf32(v - hi);
                int j = i - 64;
                int m = j >> 5, c = j & 31;
                int mt = m >> 4, gg = m & 7, il = (m >> 3) & 1;
                int kk = c >> 3, tt = c & 3, ih = (c >> 2) & 1;
                int idx = ((mt * 4 + kk) * 32 + 4 * gg + tt) * 8 + (il + 2 * ih);
                s_ginf[idx]     = hi;
                s_ginf[idx + 4] = lo;
            } else {
                int j = i - 2112;
                int o = j >> 6, m = j & 63;
                int ot = o >> 4, gg = o & 7, il = (o >> 3) & 1;
                int kk = m >> 3, tt = m & 3, ih = (m >> 2) & 1;
                s_gotf[((ot * 8 + kk) * 32 + 4 * gg + tt) * 4 + (il + 2 * ih)] = hi;
            }
        }
    }

    // ---- stage input tile into B-fragment order, tf32-rounded ----
    const float* inb = inputs + (size_t)b * (IC * HW) + p0;
    #pragma unroll
    for (int i = tid; i < 32 * 32; i += 512) {
        int c = i >> 5, p4 = i & 31;
        float4 v = *(const float4*)&inb[c * 4096 + p4 * 4];
        int kk = c >> 3, r = (c >> 2) & 1, tt = c & 3;
        int p  = p4 * 4;
        int pb = p >> 3, g0 = p & 7;   // 4 consecutive p stay in one 8-group
        float* base = &s_inf[((kk * 16 + pb) * 32 + tt) * 2 + r];
        base[(g0 + 0) * 8] = round_tf32(v.x);
        base[(g0 + 1) * 8] = round_tf32(v.y);
        base[(g0 + 2) * 8] = round_tf32(v.z);
        base[(g0 + 3) * 8] = round_tf32(v.w);
    }
    __syncthreads();

    // ==== phase 1: gated(64x128) = gin(64x32) @ in(32x128), exact-A ====
    {
        const int mt  = w & 3;
        const int pb0 = (w >> 2) * 4;
        const int pg  = pb0 * 8;
        float d[4][4] = {};

        #pragma unroll
        for (int kk = 0; kk < 4; kk++) {
            const float* ab = &s_ginf[((mt * 4 + kk) * 32 + lane) * 8];
            float4 ah = *(const float4*)ab;
            float4 al = *(const float4*)(ab + 4);
            #pragma unroll
            for (int u = 0; u < 4; u++) {
                float2 bv = *(const float2*)&s_inf[((kk * 16 + pb0 + u) * 32 + lane) * 2];
                mma_tf32(d[u], ah, bv);
                mma_tf32(d[u], al, bv);
            }
        }

        const int r1 = mt * 16 + g, r2 = r1 + 8;
        const float f1 = s_f[r1], f2 = s_f[r2];
        const float* stb = state + (size_t)b * (NM * HW) + p0;
        float*       nsb = new_state + (size_t)b * (NM * HW) + p0;

        #pragma unroll
        for (int u = 0; u < 4; u++) {
            const int c2 = pg + u * 8 + 2 * tg;
            float2 st1 = *(const float2*)&stb[(size_t)r1 * 4096 + c2];
            float2 st2 = *(const float2*)&stb[(size_t)r2 * 4096 + c2];
            float2 ns1, ns2;
            ns1.x = fmaf(st1.x, f1, d[u][0]);
            ns1.y = fmaf(st1.y, f1, d[u][1]);
            ns2.x = fmaf(st2.x, f2, d[u][2]);
            ns2.y = fmaf(st2.y, f2, d[u][3]);
            *(float2*)&nsb[(size_t)r1 * 4096 + c2] = ns1;
            *(float2*)&nsb[(size_t)r2 * 4096 + c2] = ns2;
            float2 t1, t2;
            t1.x = round_tf32(tanh_fast(ns1.x));
            t1.y = round_tf32(tanh_fast(ns1.y));
            t2.x = round_tf32(tanh_fast(ns2.x));
            t2.y = round_tf32(tanh_fast(ns2.y));
            *(float2*)&s_t[r1 * PIX_PAD + c2] = t1;
            *(float2*)&s_t[r2 * PIX_PAD + c2] = t2;
        }
    }
    __syncthreads();

    // ==== phase 2: out(32x128) = gout_hi(32x64) @ t(64x128) ====
    {
        const int ot  = w & 1;
        const int pg2 = (w >> 1) * 16;
        float d[2][4] = {};

        #pragma unroll
        for (int kk = 0; kk < 8; kk++) {
            const int k0 = kk * 8;
            float4 ah = *(const float4*)&s_gotf[((ot * 8 + kk) * 32 + lane) * 4];
            #pragma unroll
            for (int v = 0; v < 2; v++) {
                const int pb = pg2 + v * 8;
                float2 bv;
                bv.x = s_t[(k0 + tg)     * PIX_PAD + pb + g];
                bv.y = s_t[(k0 + tg + 4) * PIX_PAD + pb + g];
                mma_tf32(d[v], ah, bv);
            }
        }

        const int r1 = ot * 16 + g, r2 = r1 + 8;
        float* ob = outputs + (size_t)b * (OC * HW) + p0;
        #pragma unroll
        for (int v = 0; v < 2; v++) {
            const int c2 = pg2 + v * 8 + 2 * tg;
            *(float2*)&ob[(size_t)r1 * 4096 + c2] = make_float2(d[v][0], d[v][1]);
            *(float2*)&ob[(size_t)r2 * 4096 + c2] = make_float2(d[v][2], d[v][3]);
        }
    }
}

// ---------------------------------------------------------------------------
extern "C" void kernel_launch(void* const* d_in, const int* in_sizes, int n_in,
                              void* d_out, int out_size) {
    const float* inputs   = (const float*)d_in[0];   // [64,32,64,64]
    const float* state    = (const float*)d_in[1];   // [64,64,64,64]
    const float* controls = (const float*)d_in[2];   // [64,512]
    const float* W        = (const float*)d_in[3];   // [4160,512]

    float* outputs   = (float*)d_out;
    float* new_state = outputs + OUT_ELEMS;

    ctrl_gemm<<<dim3(130, KSPLIT), 256>>>(controls, W);
    ctrl_reduce_t<<<65, 256>>>();

    const size_t smem = (4096 + 64 * PIX_PAD + 4096 + 2048 + 64) * sizeof(float);
    cudaFuncSetAttribute(vstm_main, cudaFuncAttributeMaxDynamicSharedMemorySize, (int)smem);
    vstm_main<<<dim3(HW / 128, BATCH), 512, smem>>>(inputs, state, outputs, new_state);
}

// round 10
// speedup vs baseline: 1.3461x; 1.3461x over previous
#include <cuda_runtime.h>
#include <math.h>
#include <stdint.h>

#define BATCH 64
#define IC 32
#define OC 32
#define NM 64
#define HW 4096
#define CTRLD 512
#define ROWS 4160        // NF(64) + NI(2048) + NO(2048)
#define KSPLIT 4
#define BR (BATCH * ROWS)
#define OUT_ELEMS (BATCH * OC * HW)

// scratch: K-split partials [ksplit][row][batch], reduced gates [batch][row]
__device__ float g_ctrl[KSPLIT * BR];
__device__ float g_gates[BR];

__device__ __forceinline__ float tanh_fast(float x) {
    float y;
    asm("tanh.approx.f32 %0, %1;" : "=f"(y) : "f"(x));
    return y;
}

// round fp32 -> tf32 (value kept in a float register, low mantissa bits zeroed)
__device__ __forceinline__ float round_tf32(float x) {
    uint32_t h;
    asm("cvt.rna.tf32.f32 %0, %1;" : "=r"(h) : "f"(x));
    return __uint_as_float(h);
}

__device__ __forceinline__ void mma_tf32(float* d, const uint32_t* a, const uint32_t* b) {
    asm("mma.sync.aligned.m16n8k8.row.col.f32.tf32.tf32.f32 "
        "{%0,%1,%2,%3},{%4,%5,%6,%7},{%8,%9},{%0,%1,%2,%3};"
        : "+f"(d[0]), "+f"(d[1]), "+f"(d[2]), "+f"(d[3])
        : "r"(a[0]), "r"(a[1]), "r"(a[2]), "r"(a[3]), "r"(b[0]), "r"(b[1]));
}

// ---------------------------------------------------------------------------
// Kernel 1: ctrl partials = controls @ W.T, K split 4 ways (grid 65 x 4).
// Double-buffered; partials stored [kz][r][b] with coalesced float4 stores.
// (R8 configuration — measured 13.5us.)
// ---------------------------------------------------------------------------
__global__ __launch_bounds__(256) void ctrl_gemm(
    const float* __restrict__ controls,   // [64, 512]
    const float* __restrict__ W)          // [4160, 512]
{
    __shared__ float sW[2][16 * 68];
    __shared__ float sC[2][16 * 68];

    const int r0    = blockIdx.x * 64;
    const int kz    = blockIdx.y;
    const int kbase = kz * (CTRLD / KSPLIT);   // 128 per split
    const int tid   = threadIdx.x;
    const int ty    = tid >> 4;
    const int tx    = tid & 15;

    const int sr = tid >> 2;
    const int sk = (tid & 3) * 4;

    const float* wp = W + (size_t)(r0 + sr) * CTRLD + kbase + sk;
    const float* cp = controls + sr * CTRLD + kbase + sk;

    float acc[4][4] = {};

    {
        float4 wv = *(const float4*)wp;
        float4 cv = *(const float4*)cp;
        sW[0][(sk + 0) * 68 + sr] = wv.x;
        sW[0][(sk + 1) * 68 + sr] = wv.y;
        sW[0][(sk + 2) * 68 + sr] = wv.z;
        sW[0][(sk + 3) * 68 + sr] = wv.w;
        sC[0][(sk + 0) * 68 + sr] = cv.x;
        sC[0][(sk + 1) * 68 + sr] = cv.y;
        sC[0][(sk + 2) * 68 + sr] = cv.z;
        sC[0][(sk + 3) * 68 + sr] = cv.w;
    }
    __syncthreads();

    #pragma unroll
    for (int c = 0; c < 8; c++) {
        const int cur = c & 1;
        const int nxt = cur ^ 1;

        float4 wv, cv;
        if (c < 7) {
            wv = *(const float4*)(wp + (c + 1) * 16);
            cv = *(const float4*)(cp + (c + 1) * 16);
        }

        #pragma unroll
        for (int k = 0; k < 16; k++) {
            float4 a  = *(const float4*)&sW[cur][k * 68 + ty * 4];
            float4 bb = *(const float4*)&sC[cur][k * 68 + tx * 4];
            float av[4] = {a.x, a.y, a.z, a.w};
            float bv[4] = {bb.x, bb.y, bb.z, bb.w};
            #pragma unroll
            for (int i = 0; i < 4; i++)
                #pragma unroll
                for (int j = 0; j < 4; j++)
                    acc[i][j] = fmaf(av[i], bv[j], acc[i][j]);
        }

        if (c < 7) {
            sW[nxt][(sk + 0) * 68 + sr] = wv.x;
            sW[nxt][(sk + 1) * 68 + sr] = wv.y;
            sW[nxt][(sk + 2) * 68 + sr] = wv.z;
            sW[nxt][(sk + 3) * 68 + sr] = wv.w;
            sC[nxt][(sk + 0) * 68 + sr] = cv.x;
            sC[nxt][(sk + 1) * 68 + sr] = cv.y;
            sC[nxt][(sk + 2) * 68 + sr] = cv.z;
            sC[nxt][(sk + 3) * 68 + sr] = cv.w;
            __syncthreads();
        }
    }

    // coalesced float4 stores: [kz][r][b]
    #pragma unroll
    for (int i = 0; i < 4; i++) {
        int r = r0 + ty * 4 + i;
        float4 v = make_float4(acc[i][0], acc[i][1], acc[i][2], acc[i][3]);
        *(float4*)&g_ctrl[(size_t)kz * BR + r * 64 + tx * 4] = v;
    }
}

// ---------------------------------------------------------------------------
// Kernel 1b: reduce 4 partials [kz][r][b] and transpose -> g_gates [b][r].
// ---------------------------------------------------------------------------
__global__ __launch_bounds__(256) void ctrl_reduce_t()
{
    __shared__ float s[64 * 65];
    const int r0  = blockIdx.x * 64;
    const int tid = threadIdx.x;

    #pragma unroll
    for (int t = 0; t < 16; t++) {
        int i  = t * 256 + tid;
        int rr = i >> 6, b = i & 63;
        float v = 0.f;
        #pragma unroll
        for (int k = 0; k < KSPLIT; k++)
            v += g_ctrl[(size_t)k * BR + (r0 + rr) * 64 + b];
        s[rr * 65 + b] = v;
    }
    __syncthreads();

    #pragma unroll
    for (int t = 0; t < 16; t++) {
        int i  = t * 256 + tid;
        int b  = i >> 6, rr = i & 63;
        g_gates[(size_t)b * ROWS + r0 + rr] = s[rr * 65 + b];
    }
}

// ---------------------------------------------------------------------------
// Kernel 2: tensor-core vstm (R8 layout). Phase 1: exact-A (2 MMA).
// Phase 2: gout quantized to tf32 (1 MMA) — validated in R9 (rel_err 4.4e-4).
// ---------------------------------------------------------------------------
#define PIX_PAD 136

__global__ __launch_bounds__(512, 2) void vstm_main(
    const float* __restrict__ inputs,     // [B, 32, 4096]
    const float* __restrict__ state,      // [B, 64, 4096]
    float* __restrict__ outputs,          // [B, 32, 4096]
    float* __restrict__ new_state)        // [B, 64, 4096]
{
    extern __shared__ float sm[];
    float* s_in   = sm;                          // [32][136] tf32-rounded
    float* s_t    = s_in + 32 * PIX_PAD;         // [64][136] tf32-rounded
    float* s_ginh = s_t + 64 * PIX_PAD;          // [m][36] hi
    float* s_ginl = s_ginh + 64 * 36;            // [m][36] lo
    float* s_goth = s_ginl + 64 * 36;            // [o][68] hi (tf32)
    float* s_f    = s_goth + 32 * 68;            // [64]

    const int b    = blockIdx.y;
    const int p0   = blockIdx.x * 128;
    const int tid  = threadIdx.x;
    const int lane = tid & 31;
    const int w    = tid >> 5;       // 0..15
    const int g    = lane >> 2;      // 0..7
    const int tg   = lane & 3;       // 0..3

    // ---- stage gates: split hi/lo once (gin); gout tf32 only ----
    {
        const float* gc = g_gates + (size_t)b * ROWS;
        for (int i = tid; i < ROWS; i += 512) {
            float v  = gc[i];
            float hi = round_tf32(v);
            if (i < 64) {
                s_f[i] = v;
            } else if (i < 64 + 2048) {
                float lo = round_tf32(v - hi);
                int j = i - 64;                       // in_gates [m][c]
                s_ginh[(j >> 5) * 36 + (j & 31)] = hi;
                s_ginl[(j >> 5) * 36 + (j & 31)] = lo;
            } else {
                int j = i - 2112;                     // out_gates [o][m]
                s_goth[(j >> 6) * 68 + (j & 63)] = hi;
            }
        }
    }

    // ---- stage input tile [32][128], tf32-rounded ----
    const float* inb = inputs + (size_t)b * (IC * HW) + p0;
    #pragma unroll
    for (int i = tid; i < 32 * 32; i += 512) {
        int c = i >> 5, p4 = i & 31;
        float4 v = *(const float4*)&inb[c * 4096 + p4 * 4];
        v.x = round_tf32(v.x); v.y = round_tf32(v.y);
        v.z = round_tf32(v.z); v.w = round_tf32(v.w);
        *(float4*)&s_in[c * PIX_PAD + p4 * 4] = v;
    }
    __syncthreads();

    // ==== phase 1: gated(64x128) = gin(64x32) @ in(32x128) ====
    {
        const int m0 = (w & 3) * 16;
        const int pg = (w >> 2) * 32;
        float d[4][4] = {};

        #pragma unroll
        for (int kk = 0; kk < 4; kk++) {
            const int k0 = kk * 8;
            uint32_t ah[4], al[4];
            ah[0] = __float_as_uint(s_ginh[(m0 + g)     * 36 + k0 + tg]);
            ah[1] = __float_as_uint(s_ginh[(m0 + g + 8) * 36 + k0 + tg]);
            ah[2] = __float_as_uint(s_ginh[(m0 + g)     * 36 + k0 + tg + 4]);
            ah[3] = __float_as_uint(s_ginh[(m0 + g + 8) * 36 + k0 + tg + 4]);
            al[0] = __float_as_uint(s_ginl[(m0 + g)     * 36 + k0 + tg]);
            al[1] = __float_as_uint(s_ginl[(m0 + g + 8) * 36 + k0 + tg]);
            al[2] = __float_as_uint(s_ginl[(m0 + g)     * 36 + k0 + tg + 4]);
            al[3] = __float_as_uint(s_ginl[(m0 + g + 8) * 36 + k0 + tg + 4]);

            #pragma unroll
            for (int u = 0; u < 4; u++) {
                const int pb = pg + u * 8;
                uint32_t bh[2];
                bh[0] = __float_as_uint(s_in[(k0 + tg)     * PIX_PAD + pb + g]);
                bh[1] = __float_as_uint(s_in[(k0 + tg + 4) * PIX_PAD + pb + g]);
                mma_tf32(d[u], ah, bh);
                mma_tf32(d[u], al, bh);
            }
        }

        // epilogue: new_state = d + state*f; tanh (tf32-rounded) -> s_t
        const int r1 = m0 + g, r2 = m0 + g + 8;
        const float f1 = s_f[r1], f2 = s_f[r2];
        const float* stb = state + (size_t)b * (NM * HW) + p0;
        float*       nsb = new_state + (size_t)b * (NM * HW) + p0;

        #pragma unroll
        for (int u = 0; u < 4; u++) {
            const int c2 = pg + u * 8 + 2 * tg;
            float2 st1 = *(const float2*)&stb[(size_t)r1 * 4096 + c2];
            float2 st2 = *(const float2*)&stb[(size_t)r2 * 4096 + c2];
            float2 ns1, ns2;
            ns1.x = fmaf(st1.x, f1, d[u][0]);
            ns1.y = fmaf(st1.y, f1, d[u][1]);
            ns2.x = fmaf(st2.x, f2, d[u][2]);
            ns2.y = fmaf(st2.y, f2, d[u][3]);
            *(float2*)&nsb[(size_t)r1 * 4096 + c2] = ns1;
            *(float2*)&nsb[(size_t)r2 * 4096 + c2] = ns2;
            float2 t1, t2;
            t1.x = round_tf32(tanh_fast(ns1.x));
            t1.y = round_tf32(tanh_fast(ns1.y));
            t2.x = round_tf32(tanh_fast(ns2.x));
            t2.y = round_tf32(tanh_fast(ns2.y));
            *(float2*)&s_t[r1 * PIX_PAD + c2] = t1;
            *(float2*)&s_t[r2 * PIX_PAD + c2] = t2;
        }
    }
    __syncthreads();

    // ==== phase 2: out(32x128) = gout_tf32(32x64) @ t(64x128), 1 MMA ====
    {
        const int o0  = (w & 1) * 16;
        const int pg2 = (w >> 1) * 16;
        float d[2][4] = {};

        #pragma unroll
        for (int kk = 0; kk < 8; kk++) {
            const int k0 = kk * 8;
            uint32_t ah[4];
            ah[0] = __float_as_uint(s_goth[(o0 + g)     * 68 + k0 + tg]);
            ah[1] = __float_as_uint(s_goth[(o0 + g + 8) * 68 + k0 + tg]);
            ah[2] = __float_as_uint(s_goth[(o0 + g)     * 68 + k0 + tg + 4]);
            ah[3] = __float_as_uint(s_goth[(o0 + g + 8) * 68 + k0 + tg + 4]);

            #pragma unroll
            for (int v = 0; v < 2; v++) {
                const int pb = pg2 + v * 8;
                uint32_t bh[2];
                bh[0] = __float_as_uint(s_t[(k0 + tg)     * PIX_PAD + pb + g]);
                bh[1] = __float_as_uint(s_t[(k0 + tg + 4) * PIX_PAD + pb + g]);
                mma_tf32(d[v], ah, bh);
            }
        }

        const int r1 = o0 + g, r2 = o0 + g + 8;
        float* ob = outputs + (size_t)b * (OC * HW) + p0;
        #pragma unroll
        for (int v = 0; v < 2; v++) {
            const int c2 = pg2 + v * 8 + 2 * tg;
            *(float2*)&ob[(size_t)r1 * 4096 + c2] = make_float2(d[v][0], d[v][1]);
            *(float2*)&ob[(size_t)r2 * 4096 + c2] = make_float2(d[v][2], d[v][3]);
        }
    }
}

// ---------------------------------------------------------------------------
extern "C" void kernel_launch(void* const* d_in, const int* in_sizes, int n_in,
                              void* d_out, int out_size) {
    const float* inputs   = (const float*)d_in[0];   // [64,32,64,64]
    const float* state    = (const float*)d_in[1];   // [64,64,64,64]
    const float* controls = (const float*)d_in[2];   // [64,512]
    const float* W        = (const float*)d_in[3];   // [4160,512]

    float* outputs   = (float*)d_out;
    float* new_state = outputs + OUT_ELEMS;

    ctrl_gemm<<<dim3(65, KSPLIT), 256>>>(controls, W);
    ctrl_reduce_t<<<65, 256>>>();

    const size_t smem = (32 * PIX_PAD + 64 * PIX_PAD + 2 * 64 * 36 + 32 * 68 + 64)
                        * sizeof(float);
    cudaFuncSetAttribute(vstm_main, cudaFuncAttributeMaxDynamicSharedMemorySize, (int)smem);
    vstm_main<<<dim3(HW / 128, BATCH), 512, smem>>>(inputs, state, outputs, new_state);
}

// round 11
// speedup vs baseline: 1.3700x; 1.0178x over previous
#include <cuda_runtime.h>
#include <math.h>
#include <stdint.h>

#define BATCH 64
#define IC 32
#define OC 32
#define NM 64
#define HW 4096
#define CTRLD 512
#define ROWS 4160        // NF(64) + NI(2048) + NO(2048)
#define KSPLIT 4
#define BR (BATCH * ROWS)
#define OUT_ELEMS (BATCH * OC * HW)

// scratch: K-split partials [ksplit][row][batch], reduced gates [batch][row]
__device__ float g_ctrl[KSPLIT * BR];
__device__ float g_gates[BR];

__device__ __forceinline__ float tanh_fast(float x) {
    float y;
    asm("tanh.approx.f32 %0, %1;" : "=f"(y) : "f"(x));
    return y;
}

// round fp32 -> tf32 (value kept in a float register, low mantissa bits zeroed)
__device__ __forceinline__ float round_tf32(float x) {
    uint32_t h;
    asm("cvt.rna.tf32.f32 %0, %1;" : "=r"(h) : "f"(x));
    return __uint_as_float(h);
}

__device__ __forceinline__ void mma_tf32(float* d, const uint32_t* a, const uint32_t* b) {
    asm("mma.sync.aligned.m16n8k8.row.col.f32.tf32.tf32.f32 "
        "{%0,%1,%2,%3},{%4,%5,%6,%7},{%8,%9},{%0,%1,%2,%3};"
        : "+f"(d[0]), "+f"(d[1]), "+f"(d[2]), "+f"(d[3])
        : "r"(a[0]), "r"(a[1]), "r"(a[2]), "r"(a[3]), "r"(b[0]), "r"(b[1]));
}

// ---------------------------------------------------------------------------
// Kernel 1: ctrl partials = controls @ W.T, K split 4 ways (grid 65 x 4).
// Double-buffered; partials stored [kz][r][b] with coalesced float4 stores.
// (R8 configuration — measured 13.5us.)
// ---------------------------------------------------------------------------
__global__ __launch_bounds__(256) void ctrl_gemm(
    const float* __restrict__ controls,   // [64, 512]
    const float* __restrict__ W)          // [4160, 512]
{
    __shared__ float sW[2][16 * 68];
    __shared__ float sC[2][16 * 68];

    const int r0    = blockIdx.x * 64;
    const int kz    = blockIdx.y;
    const int kbase = kz * (CTRLD / KSPLIT);   // 128 per split
    const int tid   = threadIdx.x;
    const int ty    = tid >> 4;
    const int tx    = tid & 15;

    const int sr = tid >> 2;
    const int sk = (tid & 3) * 4;

    const float* wp = W + (size_t)(r0 + sr) * CTRLD + kbase + sk;
    const float* cp = controls + sr * CTRLD + kbase + sk;

    float acc[4][4] = {};

    {
        float4 wv = *(const float4*)wp;
        float4 cv = *(const float4*)cp;
        sW[0][(sk + 0) * 68 + sr] = wv.x;
        sW[0][(sk + 1) * 68 + sr] = wv.y;
        sW[0][(sk + 2) * 68 + sr] = wv.z;
        sW[0][(sk + 3) * 68 + sr] = wv.w;
        sC[0][(sk + 0) * 68 + sr] = cv.x;
        sC[0][(sk + 1) * 68 + sr] = cv.y;
        sC[0][(sk + 2) * 68 + sr] = cv.z;
        sC[0][(sk + 3) * 68 + sr] = cv.w;
    }
    __syncthreads();

    #pragma unroll
    for (int c = 0; c < 8; c++) {
        const int cur = c & 1;
        const int nxt = cur ^ 1;

        float4 wv, cv;
        if (c < 7) {
            wv = *(const float4*)(wp + (c + 1) * 16);
            cv = *(const float4*)(cp + (c + 1) * 16);
        }

        #pragma unroll
        for (int k = 0; k < 16; k++) {
            float4 a  = *(const float4*)&sW[cur][k * 68 + ty * 4];
            float4 bb = *(const float4*)&sC[cur][k * 68 + tx * 4];
            float av[4] = {a.x, a.y, a.z, a.w};
            float bv[4] = {bb.x, bb.y, bb.z, bb.w};
            #pragma unroll
            for (int i = 0; i < 4; i++)
                #pragma unroll
                for (int j = 0; j < 4; j++)
                    acc[i][j] = fmaf(av[i], bv[j], acc[i][j]);
        }

        if (c < 7) {
            sW[nxt][(sk + 0) * 68 + sr] = wv.x;
            sW[nxt][(sk + 1) * 68 + sr] = wv.y;
            sW[nxt][(sk + 2) * 68 + sr] = wv.z;
            sW[nxt][(sk + 3) * 68 + sr] = wv.w;
            sC[nxt][(sk + 0) * 68 + sr] = cv.x;
            sC[nxt][(sk + 1) * 68 + sr] = cv.y;
            sC[nxt][(sk + 2) * 68 + sr] = cv.z;
            sC[nxt][(sk + 3) * 68 + sr] = cv.w;
            __syncthreads();
        }
    }

    // coalesced float4 stores: [kz][r][b]
    #pragma unroll
    for (int i = 0; i < 4; i++) {
        int r = r0 + ty * 4 + i;
        float4 v = make_float4(acc[i][0], acc[i][1], acc[i][2], acc[i][3]);
        *(float4*)&g_ctrl[(size_t)kz * BR + r * 64 + tx * 4] = v;
    }
}

// ---------------------------------------------------------------------------
// Kernel 1b: reduce 4 partials [kz][r][b] and transpose -> g_gates [b][r].
// ---------------------------------------------------------------------------
__global__ __launch_bounds__(256) void ctrl_reduce_t()
{
    __shared__ float s[64 * 65];
    const int r0  = blockIdx.x * 64;
    const int tid = threadIdx.x;

    #pragma unroll
    for (int t = 0; t < 16; t++) {
        int i  = t * 256 + tid;
        int rr = i >> 6, b = i & 63;
        float v = 0.f;
        #pragma unroll
        for (int k = 0; k < KSPLIT; k++)
            v += g_ctrl[(size_t)k * BR + (r0 + rr) * 64 + b];
        s[rr * 65 + b] = v;
    }
    __syncthreads();

    #pragma unroll
    for (int t = 0; t < 16; t++) {
        int i  = t * 256 + tid;
        int b  = i >> 6, rr = i & 63;
        g_gates[(size_t)b * ROWS + r0 + rr] = s[rr * 65 + b];
    }
}

// ---------------------------------------------------------------------------
// Kernel 2: tensor-core vstm (R8 layout). Phase 1: exact-A (2 MMA).
// Phase 2: gout quantized to tf32 (1 MMA) — validated in R9 (rel_err 4.4e-4).
// ---------------------------------------------------------------------------
#define PIX_PAD 136

__global__ __launch_bounds__(512, 2) void vstm_main(
    const float* __restrict__ inputs,     // [B, 32, 4096]
    const float* __restrict__ state,      // [B, 64, 4096]
    float* __restrict__ outputs,          // [B, 32, 4096]
    float* __restrict__ new_state)        // [B, 64, 4096]
{
    extern __shared__ float sm[];
    float* s_in   = sm;                          // [32][136] tf32-rounded
    float* s_t    = s_in + 32 * PIX_PAD;         // [64][136] tf32-rounded
    float* s_ginh = s_t + 64 * PIX_PAD;          // [m][36] hi
    float* s_ginl = s_ginh + 64 * 36;            // [m][36] lo
    float* s_goth = s_ginl + 64 * 36;            // [o][68] hi (tf32)
    float* s_f    = s_goth + 32 * 68;            // [64]

    const int b    = blockIdx.y;
    const int p0   = blockIdx.x * 128;
    const int tid  = threadIdx.x;
    const int lane = tid & 31;
    const int w    = tid >> 5;       // 0..15
    const int g    = lane >> 2;      // 0..7
    const int tg   = lane & 3;       // 0..3

    // ---- stage gates: split hi/lo once (gin); gout tf32 only ----
    {
        const float* gc = g_gates + (size_t)b * ROWS;
        for (int i = tid; i < ROWS; i += 512) {
            float v  = gc[i];
            float hi = round_tf32(v);
            if (i < 64) {
                s_f[i] = v;
            } else if (i < 64 + 2048) {
                float lo = round_tf32(v - hi);
                int j = i - 64;                       // in_gates [m][c]
                s_ginh[(j >> 5) * 36 + (j & 31)] = hi;
                s_ginl[(j >> 5) * 36 + (j & 31)] = lo;
            } else {
                int j = i - 2112;                     // out_gates [o][m]
                s_goth[(j >> 6) * 68 + (j & 63)] = hi;
            }
        }
    }

    // ---- stage input tile [32][128], tf32-rounded ----
    const float* inb = inputs + (size_t)b * (IC * HW) + p0;
    #pragma unroll
    for (int i = tid; i < 32 * 32; i += 512) {
        int c = i >> 5, p4 = i & 31;
        float4 v = *(const float4*)&inb[c * 4096 + p4 * 4];
        v.x = round_tf32(v.x); v.y = round_tf32(v.y);
        v.z = round_tf32(v.z); v.w = round_tf32(v.w);
        *(float4*)&s_in[c * PIX_PAD + p4 * 4] = v;
    }
    __syncthreads();

    // ==== phase 1: gated(64x128) = gin(64x32) @ in(32x128) ====
    {
        const int m0 = (w & 3) * 16;
        const int pg = (w >> 2) * 32;
        float d[4][4] = {};

        #pragma unroll
        for (int kk = 0; kk < 4; kk++) {
            const int k0 = kk * 8;
            uint32_t ah[4], al[4];
            ah[0] = __float_as_uint(s_ginh[(m0 + g)     * 36 + k0 + tg]);
            ah[1] = __float_as_uint(s_ginh[(m0 + g + 8) * 36 + k0 + tg]);
            ah[2] = __float_as_uint(s_ginh[(m0 + g)     * 36 + k0 + tg + 4]);
            ah[3] = __float_as_uint(s_ginh[(m0 + g + 8) * 36 + k0 + tg + 4]);
            al[0] = __float_as_uint(s_ginl[(m0 + g)     * 36 + k0 + tg]);
            al[1] = __float_as_uint(s_ginl[(m0 + g + 8) * 36 + k0 + tg]);
            al[2] = __float_as_uint(s_ginl[(m0 + g)     * 36 + k0 + tg + 4]);
            al[3] = __float_as_uint(s_ginl[(m0 + g + 8) * 36 + k0 + tg + 4]);

            #pragma unroll
            for (int u = 0; u < 4; u++) {
                const int pb = pg + u * 8;
                uint32_t bh[2];
                bh[0] = __float_as_uint(s_in[(k0 + tg)     * PIX_PAD + pb + g]);
                bh[1] = __float_as_uint(s_in[(k0 + tg + 4) * PIX_PAD + pb + g]);
                mma_tf32(d[u], ah, bh);
                mma_tf32(d[u], al, bh);
            }
        }

        // epilogue: new_state = d + state*f; tanh (tf32-rounded) -> s_t
        const int r1 = m0 + g, r2 = m0 + g + 8;
        const float f1 = s_f[r1], f2 = s_f[r2];
        const float* stb = state + (size_t)b * (NM * HW) + p0;
        float*       nsb = new_state + (size_t)b * (NM * HW) + p0;

        #pragma unroll
        for (int u = 0; u < 4; u++) {
            const int c2 = pg + u * 8 + 2 * tg;
            float2 st1 = *(const float2*)&stb[(size_t)r1 * 4096 + c2];
            float2 st2 = *(const float2*)&stb[(size_t)r2 * 4096 + c2];
            float2 ns1, ns2;
            ns1.x = fmaf(st1.x, f1, d[u][0]);
            ns1.y = fmaf(st1.y, f1, d[u][1]);
            ns2.x = fmaf(st2.x, f2, d[u][2]);
            ns2.y = fmaf(st2.y, f2, d[u][3]);
            *(float2*)&nsb[(size_t)r1 * 4096 + c2] = ns1;
            *(float2*)&nsb[(size_t)r2 * 4096 + c2] = ns2;
            float2 t1, t2;
            t1.x = round_tf32(tanh_fast(ns1.x));
            t1.y = round_tf32(tanh_fast(ns1.y));
            t2.x = round_tf32(tanh_fast(ns2.x));
            t2.y = round_tf32(tanh_fast(ns2.y));
            *(float2*)&s_t[r1 * PIX_PAD + c2] = t1;
            *(float2*)&s_t[r2 * PIX_PAD + c2] = t2;
        }
    }
    __syncthreads();

    // ==== phase 2: out(32x128) = gout_tf32(32x64) @ t(64x128), 1 MMA ====
    {
        const int o0  = (w & 1) * 16;
        const int pg2 = (w >> 1) * 16;
        float d[2][4] = {};

        #pragma unroll
        for (int kk = 0; kk < 8; kk++) {
            const int k0 = kk * 8;
            uint32_t ah[4];
            ah[0] = __float_as_uint(s_goth[(o0 + g)     * 68 + k0 + tg]);
            ah[1] = __float_as_uint(s_goth[(o0 + g + 8) * 68 + k0 + tg]);
            ah[2] = __float_as_uint(s_goth[(o0 + g)     * 68 + k0 + tg + 4]);
            ah[3] = __float_as_uint(s_goth[(o0 + g + 8) * 68 + k0 + tg + 4]);

            #pragma unroll
            for (int v = 0; v < 2; v++) {
                const int pb = pg2 + v * 8;
                uint32_t bh[2];
                bh[0] = __float_as_uint(s_t[(k0 + tg)     * PIX_PAD + pb + g]);
                bh[1] = __float_as_uint(s_t[(k0 + tg + 4) * PIX_PAD + pb + g]);
                mma_tf32(d[v], ah, bh);
            }
        }

        const int r1 = o0 + g, r2 = o0 + g + 8;
        float* ob = outputs + (size_t)b * (OC * HW) + p0;
        #pragma unroll
        for (int v = 0; v < 2; v++) {
            const int c2 = pg2 + v * 8 + 2 * tg;
            *(float2*)&ob[(size_t)r1 * 4096 + c2] = make_float2(d[v][0], d[v][1]);
            *(float2*)&ob[(size_t)r2 * 4096 + c2] = make_float2(d[v][2], d[v][3]);
        }
    }
}

// ---------------------------------------------------------------------------
extern "C" void kernel_launch(void* const* d_in, const int* in_sizes, int n_in,
                              void* d_out, int out_size) {
    const float* inputs   = (const float*)d_in[0];   // [64,32,64,64]
    const float* state    = (const float*)d_in[1];   // [64,64,64,64]
    const float* controls = (const float*)d_in[2];   // [64,512]
    const float* W        = (const float*)d_in[3];   // [4160,512]

    float* outputs   = (float*)d_out;
    float* new_state = outputs + OUT_ELEMS;

    ctrl_gemm<<<dim3(65, KSPLIT), 256>>>(controls, W);
    ctrl_reduce_t<<<65, 256>>>();

    const size_t smem = (32 * PIX_PAD + 64 * PIX_PAD + 2 * 64 * 36 + 32 * 68 + 64)
                        * sizeof(float);
    cudaFuncSetAttribute(vstm_main, cudaFuncAttributeMaxDynamicSharedMemorySize, (int)smem);
    vstm_main<<<dim3(HW / 128, BATCH), 512, smem>>>(inputs, state, outputs, new_state);
}

// round 12
// speedup vs baseline: 1.3705x; 1.0004x over previous
#include <cuda_runtime.h>
#include <math.h>
#include <stdint.h>

#define BATCH 64
#define IC 32
#define OC 32
#define NM 64
#define HW 4096
#define CTRLD 512
#define ROWS 4160        // NF(64) + NI(2048) + NO(2048)
#define KSPLIT 4
#define BR (BATCH * ROWS)
#define OUT_ELEMS (BATCH * OC * HW)

// scratch: K-split partials [ksplit][row][batch], reduced gates [batch][row]
__device__ float g_ctrl[KSPLIT * BR];
__device__ float g_gates[BR];

__device__ __forceinline__ float tanh_fast(float x) {
    float y;
    asm("tanh.approx.f32 %0, %1;" : "=f"(y) : "f"(x));
    return y;
}

// round fp32 -> tf32 (value kept in a float register, low mantissa bits zeroed)
__device__ __forceinline__ float round_tf32(float x) {
    uint32_t h;
    asm("cvt.rna.tf32.f32 %0, %1;" : "=r"(h) : "f"(x));
    return __uint_as_float(h);
}

__device__ __forceinline__ void mma_tf32(float* d, const uint32_t* a, const uint32_t* b) {
    asm("mma.sync.aligned.m16n8k8.row.col.f32.tf32.tf32.f32 "
        "{%0,%1,%2,%3},{%4,%5,%6,%7},{%8,%9},{%0,%1,%2,%3};"
        : "+f"(d[0]), "+f"(d[1]), "+f"(d[2]), "+f"(d[3])
        : "r"(a[0]), "r"(a[1]), "r"(a[2]), "r"(a[3]), "r"(b[0]), "r"(b[1]));
}

// ---------------------------------------------------------------------------
// Kernel 1: ctrl partials = controls @ W.T, K split 4 ways (grid 65 x 4).
// Double-buffered; partials stored [kz][r][b] with coalesced float4 stores.
// (R8 configuration — measured 13.5us.)
// ---------------------------------------------------------------------------
__global__ __launch_bounds__(256) void ctrl_gemm(
    const float* __restrict__ controls,   // [64, 512]
    const float* __restrict__ W)          // [4160, 512]
{
    __shared__ float sW[2][16 * 68];
    __shared__ float sC[2][16 * 68];

    const int r0    = blockIdx.x * 64;
    const int kz    = blockIdx.y;
    const int kbase = kz * (CTRLD / KSPLIT);   // 128 per split
    const int tid   = threadIdx.x;
    const int ty    = tid >> 4;
    const int tx    = tid & 15;

    const int sr = tid >> 2;
    const int sk = (tid & 3) * 4;

    const float* wp = W + (size_t)(r0 + sr) * CTRLD + kbase + sk;
    const float* cp = controls + sr * CTRLD + kbase + sk;

    float acc[4][4] = {};

    {
        float4 wv = *(const float4*)wp;
        float4 cv = *(const float4*)cp;
        sW[0][(sk + 0) * 68 + sr] = wv.x;
        sW[0][(sk + 1) * 68 + sr] = wv.y;
        sW[0][(sk + 2) * 68 + sr] = wv.z;
        sW[0][(sk + 3) * 68 + sr] = wv.w;
        sC[0][(sk + 0) * 68 + sr] = cv.x;
        sC[0][(sk + 1) * 68 + sr] = cv.y;
        sC[0][(sk + 2) * 68 + sr] = cv.z;
        sC[0][(sk + 3) * 68 + sr] = cv.w;
    }
    __syncthreads();

    #pragma unroll
    for (int c = 0; c < 8; c++) {
        const int cur = c & 1;
        const int nxt = cur ^ 1;

        float4 wv, cv;
        if (c < 7) {
            wv = *(const float4*)(wp + (c + 1) * 16);
            cv = *(const float4*)(cp + (c + 1) * 16);
        }

        #pragma unroll
        for (int k = 0; k < 16; k++) {
            float4 a  = *(const float4*)&sW[cur][k * 68 + ty * 4];
            float4 bb = *(const float4*)&sC[cur][k * 68 + tx * 4];
            float av[4] = {a.x, a.y, a.z, a.w};
            float bv[4] = {bb.x, bb.y, bb.z, bb.w};
            #pragma unroll
            for (int i = 0; i < 4; i++)
                #pragma unroll
                for (int j = 0; j < 4; j++)
                    acc[i][j] = fmaf(av[i], bv[j], acc[i][j]);
        }

        if (c < 7) {
            sW[nxt][(sk + 0) * 68 + sr] = wv.x;
            sW[nxt][(sk + 1) * 68 + sr] = wv.y;
            sW[nxt][(sk + 2) * 68 + sr] = wv.z;
            sW[nxt][(sk + 3) * 68 + sr] = wv.w;
            sC[nxt][(sk + 0) * 68 + sr] = cv.x;
            sC[nxt][(sk + 1) * 68 + sr] = cv.y;
            sC[nxt][(sk + 2) * 68 + sr] = cv.z;
            sC[nxt][(sk + 3) * 68 + sr] = cv.w;
            __syncthreads();
        }
    }

    // coalesced float4 stores: [kz][r][b]
    #pragma unroll
    for (int i = 0; i < 4; i++) {
        int r = r0 + ty * 4 + i;
        float4 v = make_float4(acc[i][0], acc[i][1], acc[i][2], acc[i][3]);
        *(float4*)&g_ctrl[(size_t)kz * BR + r * 64 + tx * 4] = v;
    }
}

// ---------------------------------------------------------------------------
// Kernel 1b: reduce 4 partials [kz][r][b] and transpose -> g_gates [b][r].
// ---------------------------------------------------------------------------
__global__ __launch_bounds__(256) void ctrl_reduce_t()
{
    __shared__ float s[64 * 65];
    const int r0  = blockIdx.x * 64;
    const int tid = threadIdx.x;

    #pragma unroll
    for (int t = 0; t < 16; t++) {
        int i  = t * 256 + tid;
        int rr = i >> 6, b = i & 63;
        float v = 0.f;
        #pragma unroll
        for (int k = 0; k < KSPLIT; k++)
            v += g_ctrl[(size_t)k * BR + (r0 + rr) * 64 + b];
        s[rr * 65 + b] = v;
    }
    __syncthreads();

    #pragma unroll
    for (int t = 0; t < 16; t++) {
        int i  = t * 256 + tid;
        int b  = i >> 6, rr = i & 63;
        g_gates[(size_t)b * ROWS + r0 + rr] = s[rr * 65 + b];
    }
}

// ---------------------------------------------------------------------------
// Kernel 2: tensor-core vstm (R8 layout). Phase 1: exact-A (2 MMA).
// Phase 2: gout quantized to tf32 (1 MMA) — validated in R9 (rel_err 4.4e-4).
// ---------------------------------------------------------------------------
#define PIX_PAD 136

__global__ __launch_bounds__(512, 2) void vstm_main(
    const float* __restrict__ inputs,     // [B, 32, 4096]
    const float* __restrict__ state,      // [B, 64, 4096]
    float* __restrict__ outputs,          // [B, 32, 4096]
    float* __restrict__ new_state)        // [B, 64, 4096]
{
    extern __shared__ float sm[];
    float* s_in   = sm;                          // [32][136] tf32-rounded
    float* s_t    = s_in + 32 * PIX_PAD;         // [64][136] tf32-rounded
    float* s_ginh = s_t + 64 * PIX_PAD;          // [m][36] hi
    float* s_ginl = s_ginh + 64 * 36;            // [m][36] lo
    float* s_goth = s_ginl + 64 * 36;            // [o][68] hi (tf32)
    float* s_f    = s_goth + 32 * 68;            // [64]

    const int b    = blockIdx.y;
    const int p0   = blockIdx.x * 128;
    const int tid  = threadIdx.x;
    const int lane = tid & 31;
    const int w    = tid >> 5;       // 0..15
    const int g    = lane >> 2;      // 0..7
    const int tg   = lane & 3;       // 0..3

    // ---- stage gates: split hi/lo once (gin); gout tf32 only ----
    {
        const float* gc = g_gates + (size_t)b * ROWS;
        for (int i = tid; i < ROWS; i += 512) {
            float v  = gc[i];
            float hi = round_tf32(v);
            if (i < 64) {
                s_f[i] = v;
            } else if (i < 64 + 2048) {
                float lo = round_tf32(v - hi);
                int j = i - 64;                       // in_gates [m][c]
                s_ginh[(j >> 5) * 36 + (j & 31)] = hi;
                s_ginl[(j >> 5) * 36 + (j & 31)] = lo;
            } else {
                int j = i - 2112;                     // out_gates [o][m]
                s_goth[(j >> 6) * 68 + (j & 63)] = hi;
            }
        }
    }

    // ---- stage input tile [32][128], tf32-rounded ----
    const float* inb = inputs + (size_t)b * (IC * HW) + p0;
    #pragma unroll
    for (int i = tid; i < 32 * 32; i += 512) {
        int c = i >> 5, p4 = i & 31;
        float4 v = *(const float4*)&inb[c * 4096 + p4 * 4];
        v.x = round_tf32(v.x); v.y = round_tf32(v.y);
        v.z = round_tf32(v.z); v.w = round_tf32(v.w);
        *(float4*)&s_in[c * PIX_PAD + p4 * 4] = v;
    }
    __syncthreads();

    // ==== phase 1: gated(64x128) = gin(64x32) @ in(32x128) ====
    {
        const int m0 = (w & 3) * 16;
        const int pg = (w >> 2) * 32;
        float d[4][4] = {};

        #pragma unroll
        for (int kk = 0; kk < 4; kk++) {
            const int k0 = kk * 8;
            uint32_t ah[4], al[4];
            ah[0] = __float_as_uint(s_ginh[(m0 + g)     * 36 + k0 + tg]);
            ah[1] = __float_as_uint(s_ginh[(m0 + g + 8) * 36 + k0 + tg]);
            ah[2] = __float_as_uint(s_ginh[(m0 + g)     * 36 + k0 + tg + 4]);
            ah[3] = __float_as_uint(s_ginh[(m0 + g + 8) * 36 + k0 + tg + 4]);
            al[0] = __float_as_uint(s_ginl[(m0 + g)     * 36 + k0 + tg]);
            al[1] = __float_as_uint(s_ginl[(m0 + g + 8) * 36 + k0 + tg]);
            al[2] = __float_as_uint(s_ginl[(m0 + g)     * 36 + k0 + tg + 4]);
            al[3] = __float_as_uint(s_ginl[(m0 + g + 8) * 36 + k0 + tg + 4]);

            #pragma unroll
            for (int u = 0; u < 4; u++) {
                const int pb = pg + u * 8;
                uint32_t bh[2];
                bh[0] = __float_as_uint(s_in[(k0 + tg)     * PIX_PAD + pb + g]);
                bh[1] = __float_as_uint(s_in[(k0 + tg + 4) * PIX_PAD + pb + g]);
                mma_tf32(d[u], ah, bh);
                mma_tf32(d[u], al, bh);
            }
        }

        // epilogue: new_state = d + state*f; tanh (tf32-rounded) -> s_t
        const int r1 = m0 + g, r2 = m0 + g + 8;
        const float f1 = s_f[r1], f2 = s_f[r2];
        const float* stb = state + (size_t)b * (NM * HW) + p0;
        float*       nsb = new_state + (size_t)b * (NM * HW) + p0;

        #pragma unroll
        for (int u = 0; u < 4; u++) {
            const int c2 = pg + u * 8 + 2 * tg;
            float2 st1 = *(const float2*)&stb[(size_t)r1 * 4096 + c2];
            float2 st2 = *(const float2*)&stb[(size_t)r2 * 4096 + c2];
            float2 ns1, ns2;
            ns1.x = fmaf(st1.x, f1, d[u][0]);
            ns1.y = fmaf(st1.y, f1, d[u][1]);
            ns2.x = fmaf(st2.x, f2, d[u][2]);
            ns2.y = fmaf(st2.y, f2, d[u][3]);
            *(float2*)&nsb[(size_t)r1 * 4096 + c2] = ns1;
            *(float2*)&nsb[(size_t)r2 * 4096 + c2] = ns2;
            float2 t1, t2;
            t1.x = round_tf32(tanh_fast(ns1.x));
            t1.y = round_tf32(tanh_fast(ns1.y));
            t2.x = round_tf32(tanh_fast(ns2.x));
            t2.y = round_tf32(tanh_fast(ns2.y));
            *(float2*)&s_t[r1 * PIX_PAD + c2] = t1;
            *(float2*)&s_t[r2 * PIX_PAD + c2] = t2;
        }
    }
    __syncthreads();

    // ==== phase 2: out(32x128) = gout_tf32(32x64) @ t(64x128), 1 MMA ====
    {
        const int o0  = (w & 1) * 16;
        const int pg2 = (w >> 1) * 16;
        float d[2][4] = {};

        #pragma unroll
        for (int kk = 0; kk < 8; kk++) {
            const int k0 = kk * 8;
            uint32_t ah[4];
            ah[0] = __float_as_uint(s_goth[(o0 + g)     * 68 + k0 + tg]);
            ah[1] = __float_as_uint(s_goth[(o0 + g + 8) * 68 + k0 + tg]);
            ah[2] = __float_as_uint(s_goth[(o0 + g)     * 68 + k0 + tg + 4]);
            ah[3] = __float_as_uint(s_goth[(o0 + g + 8) * 68 + k0 + tg + 4]);

            #pragma unroll
            for (int v = 0; v < 2; v++) {
                const int pb = pg2 + v * 8;
                uint32_t bh[2];
                bh[0] = __float_as_uint(s_t[(k0 + tg)     * PIX_PAD + pb + g]);
                bh[1] = __float_as_uint(s_t[(k0 + tg + 4) * PIX_PAD + pb + g]);
                mma_tf32(d[v], ah, bh);
            }
        }

        const int r1 = o0 + g, r2 = o0 + g + 8;
        float* ob = outputs + (size_t)b * (OC * HW) + p0;
        #pragma unroll
        for (int v = 0; v < 2; v++) {
            const int c2 = pg2 + v * 8 + 2 * tg;
            *(float2*)&ob[(size_t)r1 * 4096 + c2] = make_float2(d[v][0], d[v][1]);
            *(float2*)&ob[(size_t)r2 * 4096 + c2] = make_float2(d[v][2], d[v][3]);
        }
    }
}

// ---------------------------------------------------------------------------
extern "C" void kernel_launch(void* const* d_in, const int* in_sizes, int n_in,
                              void* d_out, int out_size) {
    const float* inputs   = (const float*)d_in[0];   // [64,32,64,64]
    const float* state    = (const float*)d_in[1];   // [64,64,64,64]
    const float* controls = (const float*)d_in[2];   // [64,512]
    const float* W        = (const float*)d_in[3];   // [4160,512]

    float* outputs   = (float*)d_out;
    float* new_state = outputs + OUT_ELEMS;

    ctrl_gemm<<<dim3(65, KSPLIT), 256>>>(controls, W);
    ctrl_reduce_t<<<65, 256>>>();

    const size_t smem = (32 * PIX_PAD + 64 * PIX_PAD + 2 * 64 * 36 + 32 * 68 + 64)
                        * sizeof(float);
    cudaFuncSetAttribute(vstm_main, cudaFuncAttributeMaxDynamicSharedMemorySize, (int)smem);
    vstm_main<<<dim3(HW / 128, BATCH), 512, smem>>>(inputs, state, outputs, new_state);
}